// round 4
// baseline (speedup 1.0000x reference)
#include <cuda_runtime.h>

#define B_  2
#define L_  2048
#define E_  512
#define H_  8
#define D_  64
#define NF  33
#define NC  65
#define BH  (B_*H_)

typedef unsigned long long ull;
typedef ulonglong2 ull2;

__device__ __forceinline__ ull splat2(float x) {
    ull r;
    asm("mov.b64 %0, {%1, %1};" : "=l"(r) : "r"(__float_as_uint(x)));
    return r;
}
__device__ __forceinline__ void ffma2(ull& d, ull a, ull b) {
    asm("fma.rn.f32x2 %0, %1, %2, %3;" : "=l"(d) : "l"(a), "l"(b), "l"(d));
}
__device__ __forceinline__ float2 unpack2(ull v) {
    float2 f;
    asm("mov.b64 {%0, %1}, %2;" : "=f"(f.x), "=f"(f.y) : "l"(v));
    return f;
}

// -------- scratch --------
__device__ float g_basis[NC * L_];
__device__ float g_C[(size_t)BH * L_ * NC];
__device__ float g_invZ[BH * L_];
__device__ float g_Zpart[2 * BH * L_];
__device__ float g_P[(size_t)BH * L_ * L_];            // 268 MB
__device__ float g_Opart[2 * BH * D_ * L_];            // 16 MB  [z][bh][d][l]

// ============ K0: basis table ============
__global__ void basis_kernel() {
    int idx = blockIdx.x * blockDim.x + threadIdx.x;
    if (idx >= NC * L_) return;
    int t  = idx % L_;
    int kk = idx / L_;
    float v;
    if (kk == 0) {
        v = 1.0f;
    } else {
        int f = (kk + 1) >> 1;
        int r = (f * t) & (L_ - 1);
        float s, c;
        sincospif((float)r * (1.0f / 1024.0f), &s, &c);
        v = (kk & 1) ? c : s;
    }
    g_basis[kk * L_ + t] = v;
}

// ============ K1: 64-pt DFTs -> coeffs, head-mean subtracted ============
__global__ __launch_bounds__(288) void coeff_kernel(const float* __restrict__ q,
                                                    const float* __restrict__ kin) {
    int bs = blockIdx.x;
    int b  = bs >> 11;
    int s  = bs & (L_ - 1);

    __shared__ float sq[E_], sk[E_];
    __shared__ float twc[64], tws[64];
    __shared__ float A[H_][NC];

    int tid = threadIdx.x;
    for (int i = tid; i < E_; i += blockDim.x) {
        sq[i] = q[(size_t)bs * E_ + i];
        sk[i] = kin[(size_t)bs * E_ + i];
    }
    if (tid < 64) {
        float ss, cc;
        sincospif((float)tid * (1.0f / 32.0f), &ss, &cc);
        twc[tid] = cc; tws[tid] = ss;
    }
    __syncthreads();

    if (tid < H_ * NF) {
        int h = tid / NF, f = tid % NF;
        const float* qh = sq + h * D_;
        const float* kh = sk + h * D_;
        float Qr = 0.f, Qi = 0.f, Kr = 0.f, Ki = 0.f;
#pragma unroll 8
        for (int j = 0; j < 64; j++) {
            int m = (f * j) & 63;
            float c = twc[m], sn = tws[m];
            float qq = qh[j], kk2 = kh[j];
            Qr = fmaf(qq, c, Qr);  Qi = fmaf(-qq, sn, Qi);
            Kr = fmaf(kk2, c, Kr); Ki = fmaf(-kk2, sn, Ki);
        }
        float Xr = Qr * Kr + Qi * Ki;
        float Xi = Qi * Kr - Qr * Ki;
        if (f == 0) {
            A[h][0] = Xr * (1.0f / 2048.0f);
        } else {
            A[h][2 * f - 1] =  Xr * (1.0f / 1024.0f);
            A[h][2 * f]     = -Xi * (1.0f / 1024.0f);
        }
    }
    __syncthreads();

    for (int idx = tid; idx < H_ * NC; idx += blockDim.x) {
        int h = idx / NC, kk = idx % NC;
        float m = 0.f;
#pragma unroll
        for (int hh = 0; hh < H_; hh++) m += A[hh][kk];
        m *= (1.0f / H_);
        g_C[((size_t)(b * H_ + h) * L_ + s) * NC + kk] = A[h][kk] - m;
    }
}

// ============ K2: corr GEMM + exp -> P, partial rowsum ============
// grid (16 s-tiles, 16 bh, 2 t-halves), 256 thr.
// tx(16): 4 t contiguous; ty(16): 8 s contiguous.  TMZ=128 s, chunk 64 t.
#define TMZ 128
__global__ __launch_bounds__(256) void z_kernel() {
    int bh    = blockIdx.y;
    int sbase = blockIdx.x * TMZ;
    int zhalf = blockIdx.z;

    __shared__ float Cs[NC][TMZ + 4];     // 34.3 KB
    __shared__ float zs[TMZ][17];

    int tid = threadIdx.x;
    int tx  = tid & 15, ty = tid >> 4;

    for (int idx = tid; idx < TMZ * NC; idx += 256) {
        int si = idx / NC, kk = idx % NC;
        Cs[kk][si] = g_C[((size_t)bh * L_ + sbase + si) * NC + kk];
    }
    __syncthreads();

    float zpart[8] = {};
    const size_t Pbase = (size_t)bh * L_ * L_;

    for (int ch = 0; ch < 16; ch++) {
        int tbase = zhalf * 1024 + ch * 64;
        const float* bp = &g_basis[tbase + 4 * tx];

        ull acc[8][2];
#pragma unroll
        for (int i = 0; i < 8; i++) { acc[i][0] = 0ull; acc[i][1] = 0ull; }

#pragma unroll 5
        for (int kk = 0; kk < NC; kk++) {
            ull2 bv = *(const ull2*)(bp + kk * L_);          // 4 t (coalesced, L2-hot)
            float4 c0 = *(const float4*)&Cs[kk][8 * ty];    // broadcast
            float4 c1 = *(const float4*)&Cs[kk][8 * ty + 4];
            ull a0 = splat2(c0.x), a1 = splat2(c0.y), a2 = splat2(c0.z), a3 = splat2(c0.w);
            ull a4 = splat2(c1.x), a5 = splat2(c1.y), a6 = splat2(c1.z), a7 = splat2(c1.w);
            ffma2(acc[0][0], a0, bv.x); ffma2(acc[0][1], a0, bv.y);
            ffma2(acc[1][0], a1, bv.x); ffma2(acc[1][1], a1, bv.y);
            ffma2(acc[2][0], a2, bv.x); ffma2(acc[2][1], a2, bv.y);
            ffma2(acc[3][0], a3, bv.x); ffma2(acc[3][1], a3, bv.y);
            ffma2(acc[4][0], a4, bv.x); ffma2(acc[4][1], a4, bv.y);
            ffma2(acc[5][0], a5, bv.x); ffma2(acc[5][1], a5, bv.y);
            ffma2(acc[6][0], a6, bv.x); ffma2(acc[6][1], a6, bv.y);
            ffma2(acc[7][0], a7, bv.x); ffma2(acc[7][1], a7, bv.y);
        }

#pragma unroll
        for (int i = 0; i < 8; i++) {
            float2 p0 = unpack2(acc[i][0]);
            float2 p1 = unpack2(acc[i][1]);
            float4 w;
            w.x = __expf(p0.x); w.y = __expf(p0.y);
            w.z = __expf(p1.x); w.w = __expf(p1.y);
            zpart[i] += (w.x + w.y) + (w.z + w.w);
            *(float4*)&g_P[Pbase + (size_t)(sbase + 8 * ty + i) * L_ + tbase + 4 * tx] = w;
        }
    }

    __syncthreads();
#pragma unroll
    for (int i = 0; i < 8; i++) zs[8 * ty + i][tx] = zpart[i];
    __syncthreads();
    for (int s = tid; s < TMZ; s += 256) {
        float z = 0.f;
#pragma unroll
        for (int j = 0; j < 16; j++) z += zs[s][j];
        g_Zpart[(zhalf * BH + bh) * L_ + sbase + s] = z;
    }
}

// ============ K2b: combine partial Z -> invZ ============
__global__ void zcombine_kernel() {
    int i = blockIdx.x * blockDim.x + threadIdx.x;
    if (i < BH * L_) g_invZ[i] = 1.0f / (g_Zpart[i] + g_Zpart[BH * L_ + i]);
}

// ============ K3: partial out GEMM ============
// grid (16 l-tiles, 16 bh, 2 s-halves), 256 thr.
// tx(16): 4 d; ty(16): 8 l contiguous (4 packed ull). TL3=128 l, chunk 64 s.
#define TL3 128
#define SC3 64
__global__ __launch_bounds__(256) void out_kernel(const float* __restrict__ values) {
    int bh = blockIdx.y;
    int b  = bh >> 3, h = bh & 7;
    int lbase = blockIdx.x * TL3;
    int zhalf = blockIdx.z;

    __shared__ float Ws[SC3][TL3];        // 32 KB, invZ pre-multiplied

    int tid = threadIdx.x;
    int tx  = tid & 15, ty = tid >> 4;

    ull acc[4][4];                        // [l-ull][d]
#pragma unroll
    for (int i = 0; i < 4; i++)
#pragma unroll
        for (int j = 0; j < 4; j++) acc[i][j] = 0ull;

    const size_t Pbase = (size_t)bh * L_ * L_;
    const float* vbase = values + ((size_t)b * L_) * E_ + h * D_ + 4 * tx;

    for (int sch = 0; sch < 1024 / SC3; sch++) {
        int sbase = zhalf * 1024 + sch * SC3;
        __syncthreads();
        for (int idx = tid; idx < SC3 * (TL3 / 4); idx += 256) {
            int sc = idx >> 5, c4 = idx & 31;
            float4 p = *(const float4*)&g_P[Pbase + (size_t)(sbase + sc) * L_ + lbase + 4 * c4];
            float iz = g_invZ[bh * L_ + sbase + sc];
            p.x *= iz; p.y *= iz; p.z *= iz; p.w *= iz;
            *(float4*)&Ws[sc][4 * c4] = p;
        }
        __syncthreads();

#pragma unroll 4
        for (int sc = 0; sc < SC3; sc++) {
            ull2 w01 = *(const ull2*)&Ws[sc][8 * ty];       // broadcast
            ull2 w23 = *(const ull2*)&Ws[sc][8 * ty + 4];
            float4 bv = *(const float4*)&vbase[(size_t)(sbase + sc) * E_]; // coalesced LDG
            ull b0 = splat2(bv.x), b1 = splat2(bv.y), b2 = splat2(bv.z), b3 = splat2(bv.w);
            ffma2(acc[0][0], w01.x, b0); ffma2(acc[0][1], w01.x, b1);
            ffma2(acc[0][2], w01.x, b2); ffma2(acc[0][3], w01.x, b3);
            ffma2(acc[1][0], w01.y, b0); ffma2(acc[1][1], w01.y, b1);
            ffma2(acc[1][2], w01.y, b2); ffma2(acc[1][3], w01.y, b3);
            ffma2(acc[2][0], w23.x, b0); ffma2(acc[2][1], w23.x, b1);
            ffma2(acc[2][2], w23.x, b2); ffma2(acc[2][3], w23.x, b3);
            ffma2(acc[3][0], w23.y, b0); ffma2(acc[3][1], w23.y, b1);
            ffma2(acc[3][2], w23.y, b2); ffma2(acc[3][3], w23.y, b3);
        }
    }

    // store partial [z][bh][d][l]
#pragma unroll
    for (int jd = 0; jd < 4; jd++) {
        int dd = 4 * tx + jd;
        float* op = &g_Opart[(((size_t)zhalf * BH + bh) * D_ + dd) * L_ + lbase + 8 * ty];
        ull2 v0; v0.x = acc[0][jd]; v0.y = acc[1][jd];
        ull2 v1; v1.x = acc[2][jd]; v1.y = acc[3][jd];
        *(ull2*)&op[0] = v0;
        *(ull2*)&op[4] = v1;
    }
}

// ============ K3b: reduce partials + faithful scatter ============
__global__ void reduce_kernel(float* __restrict__ out) {
    int idx = blockIdx.x * blockDim.x + threadIdx.x;
    if (idx >= BH * D_ * L_) return;
    int l  = idx & (L_ - 1);
    int dd = (idx >> 11) & (D_ - 1);
    int bh = idx >> 17;
    int b  = bh >> 3, h = bh & 7;
    float v = g_Opart[idx] + g_Opart[BH * D_ * L_ + idx];
    int row = dd * 32 + h * 4 + (l >> 9);
    out[((size_t)b * 2048 + row) * 512 + (l & 511)] = v;
}

// ============ launch ============
extern "C" void kernel_launch(void* const* d_in, const int* in_sizes, int n_in,
                              void* d_out, int out_size) {
    (void)in_sizes; (void)n_in; (void)out_size;
    const float* q = (const float*)d_in[0];
    const float* k = (const float*)d_in[1];
    const float* v = (const float*)d_in[2];
    float* out = (float*)d_out;

    basis_kernel<<<(NC * L_ + 255) / 256, 256>>>();
    coeff_kernel<<<B_ * L_, 288>>>(q, k);
    z_kernel<<<dim3(L_ / TMZ, BH, 2), 256>>>();
    zcombine_kernel<<<(BH * L_ + 255) / 256, 256>>>();
    out_kernel<<<dim3(L_ / TL3, BH, 2), 256>>>(v);
    reduce_kernel<<<(BH * D_ * L_ + 255) / 256, 256>>>(out);
}

// round 5
// speedup vs baseline: 2.0456x; 2.0456x over previous
#include <cuda_runtime.h>

#define B_  2
#define L_  2048
#define E_  512
#define H_  8
#define D_  64
#define NF  33
#define NC  65
#define BH  (B_*H_)

typedef unsigned long long ull;
typedef ulonglong2 ull2;

__device__ __forceinline__ ull splat2(float x) {
    ull r;
    asm("mov.b64 %0, {%1, %1};" : "=l"(r) : "r"(__float_as_uint(x)));
    return r;
}
__device__ __forceinline__ void ffma2(ull& d, ull a, ull b) {
    asm("fma.rn.f32x2 %0, %1, %2, %3;" : "=l"(d) : "l"(a), "l"(b), "l"(d));
}
__device__ __forceinline__ float2 unpack2(ull v) {
    float2 f;
    asm("mov.b64 {%0, %1}, %2;" : "=f"(f.x), "=f"(f.y) : "l"(v));
    return f;
}

// -------- scratch --------
__device__ float g_basis[NC * L_];
__device__ float g_C[(size_t)BH * L_ * NC];
__device__ float g_invZ[BH * L_];
__device__ float g_Zpart[2 * BH * L_];
__device__ float g_P[(size_t)BH * L_ * L_];            // 268 MB
__device__ float g_Opart[2 * BH * D_ * L_];            // 16 MB  [z][bh][d][l]

// ============ K0: basis table ============
__global__ void basis_kernel() {
    int idx = blockIdx.x * blockDim.x + threadIdx.x;
    if (idx >= NC * L_) return;
    int t  = idx % L_;
    int kk = idx / L_;
    float v;
    if (kk == 0) {
        v = 1.0f;
    } else {
        int f = (kk + 1) >> 1;
        int r = (f * t) & (L_ - 1);
        float s, c;
        sincospif((float)r * (1.0f / 1024.0f), &s, &c);
        v = (kk & 1) ? c : s;
    }
    g_basis[kk * L_ + t] = v;
}

// ============ K1: 64-pt DFTs -> coeffs, head-mean subtracted ============
__global__ __launch_bounds__(288) void coeff_kernel(const float* __restrict__ q,
                                                    const float* __restrict__ kin) {
    int bs = blockIdx.x;
    int b  = bs >> 11;
    int s  = bs & (L_ - 1);

    __shared__ float sq[E_], sk[E_];
    __shared__ float twc[64], tws[64];
    __shared__ float A[H_][NC];

    int tid = threadIdx.x;
    for (int i = tid; i < E_; i += blockDim.x) {
        sq[i] = q[(size_t)bs * E_ + i];
        sk[i] = kin[(size_t)bs * E_ + i];
    }
    if (tid < 64) {
        float ss, cc;
        sincospif((float)tid * (1.0f / 32.0f), &ss, &cc);
        twc[tid] = cc; tws[tid] = ss;
    }
    __syncthreads();

    if (tid < H_ * NF) {
        int h = tid / NF, f = tid % NF;
        const float* qh = sq + h * D_;
        const float* kh = sk + h * D_;
        float Qr = 0.f, Qi = 0.f, Kr = 0.f, Ki = 0.f;
#pragma unroll 8
        for (int j = 0; j < 64; j++) {
            int m = (f * j) & 63;
            float c = twc[m], sn = tws[m];
            float qq = qh[j], kk2 = kh[j];
            Qr = fmaf(qq, c, Qr);  Qi = fmaf(-qq, sn, Qi);
            Kr = fmaf(kk2, c, Kr); Ki = fmaf(-kk2, sn, Ki);
        }
        float Xr = Qr * Kr + Qi * Ki;
        float Xi = Qi * Kr - Qr * Ki;
        if (f == 0) {
            A[h][0] = Xr * (1.0f / 2048.0f);
        } else {
            A[h][2 * f - 1] =  Xr * (1.0f / 1024.0f);
            A[h][2 * f]     = -Xi * (1.0f / 1024.0f);
        }
    }
    __syncthreads();

    for (int idx = tid; idx < H_ * NC; idx += blockDim.x) {
        int h = idx / NC, kk = idx % NC;
        float m = 0.f;
#pragma unroll
        for (int hh = 0; hh < H_; hh++) m += A[hh][kk];
        m *= (1.0f / H_);
        g_C[((size_t)(b * H_ + h) * L_ + s) * NC + kk] = A[h][kk] - m;
    }
}

// ============ K2: corr GEMM + exp -> P, partial rowsum ============
// grid (16 s-tiles, 16 bh, 2 t-halves), 256 thr.
// ty(16): 8 s (broadcast side), tx(16): 4 t (2 packed pairs). Chunk = 64 t.
#define TMZ 128
__global__ __launch_bounds__(256) void z_kernel() {
    int bh    = blockIdx.y;
    int sbase = blockIdx.x * TMZ;
    int zhalf = blockIdx.z;

    __shared__ float Cs[NC][TMZ + 4];     // 34.3 KB  (row 528B, 16B-aligned)
    __shared__ float Bs[NC][68];          // 17.7 KB  (row 272B, 16B-aligned)
    __shared__ float zs[TMZ][17];

    int tid = threadIdx.x;
    int tx  = tid & 15, ty = tid >> 4;

    for (int idx = tid; idx < TMZ * NC; idx += 256) {
        int si = idx / NC, kk = idx % NC;
        Cs[kk][si] = g_C[((size_t)bh * L_ + sbase + si) * NC + kk];
    }

    float zpart[8] = {};
    const size_t Pbase = (size_t)bh * L_ * L_;

    for (int ch = 0; ch < 16; ch++) {
        int tbase = zhalf * 1024 + ch * 64;
        __syncthreads();
        for (int idx = tid; idx < NC * 16; idx += 256) {
            int kk = idx >> 4, t4 = idx & 15;
            *(float4*)&Bs[kk][4 * t4] = *(const float4*)&g_basis[kk * L_ + tbase + 4 * t4];
        }
        __syncthreads();

        ull acc[8][2];
#pragma unroll
        for (int i = 0; i < 8; i++) { acc[i][0] = 0ull; acc[i][1] = 0ull; }

#pragma unroll 5
        for (int kk = 0; kk < NC; kk++) {
            ull2 bv = *(const ull2*)&Bs[kk][4 * tx];        // 4 t, conflict-free .128
            float4 c0 = *(const float4*)&Cs[kk][8 * ty];    // broadcast
            float4 c1 = *(const float4*)&Cs[kk][8 * ty + 4];
            ull a0 = splat2(c0.x), a1 = splat2(c0.y), a2 = splat2(c0.z), a3 = splat2(c0.w);
            ull a4 = splat2(c1.x), a5 = splat2(c1.y), a6 = splat2(c1.z), a7 = splat2(c1.w);
            ffma2(acc[0][0], a0, bv.x); ffma2(acc[0][1], a0, bv.y);
            ffma2(acc[1][0], a1, bv.x); ffma2(acc[1][1], a1, bv.y);
            ffma2(acc[2][0], a2, bv.x); ffma2(acc[2][1], a2, bv.y);
            ffma2(acc[3][0], a3, bv.x); ffma2(acc[3][1], a3, bv.y);
            ffma2(acc[4][0], a4, bv.x); ffma2(acc[4][1], a4, bv.y);
            ffma2(acc[5][0], a5, bv.x); ffma2(acc[5][1], a5, bv.y);
            ffma2(acc[6][0], a6, bv.x); ffma2(acc[6][1], a6, bv.y);
            ffma2(acc[7][0], a7, bv.x); ffma2(acc[7][1], a7, bv.y);
        }

#pragma unroll
        for (int i = 0; i < 8; i++) {
            float2 p0 = unpack2(acc[i][0]);
            float2 p1 = unpack2(acc[i][1]);
            float4 w;
            w.x = __expf(p0.x); w.y = __expf(p0.y);
            w.z = __expf(p1.x); w.w = __expf(p1.y);
            zpart[i] += (w.x + w.y) + (w.z + w.w);
            *(float4*)&g_P[Pbase + (size_t)(sbase + 8 * ty + i) * L_ + tbase + 4 * tx] = w;
        }
    }

    __syncthreads();
#pragma unroll
    for (int i = 0; i < 8; i++) zs[8 * ty + i][tx] = zpart[i];
    __syncthreads();
    for (int s = tid; s < TMZ; s += 256) {
        float z = 0.f;
#pragma unroll
        for (int j = 0; j < 16; j++) z += zs[s][j];
        g_Zpart[(zhalf * BH + bh) * L_ + sbase + s] = z;
    }
}

// ============ K2b: combine partial Z -> invZ ============
__global__ void zcombine_kernel() {
    int i = blockIdx.x * blockDim.x + threadIdx.x;
    if (i < BH * L_) g_invZ[i] = 1.0f / (g_Zpart[i] + g_Zpart[BH * L_ + i]);
}

// ============ K3: partial out GEMM (all operands staged in smem) ============
// grid (16 l-tiles, 16 bh, 2 s-halves), 256 thr.
// ty(16): 8 l (4 packed pairs), tx(16): 4 d. Chunk = 64 s.
#define TL3 128
#define SC3 64
__global__ __launch_bounds__(256) void out_kernel(const float* __restrict__ values) {
    int bh = blockIdx.y;
    int b  = bh >> 3, h = bh & 7;
    int lbase = blockIdx.x * TL3;
    int zhalf = blockIdx.z;

    __shared__ float Ws[SC3][TL3];        // 32 KB, invZ pre-multiplied
    __shared__ float Vs[SC3][68];         // 17.4 KB (row 272B, 16B-aligned)

    int tid = threadIdx.x;
    int tx  = tid & 15, ty = tid >> 4;

    ull acc[4][4];                        // [l-pair][d]
#pragma unroll
    for (int i = 0; i < 4; i++)
#pragma unroll
        for (int j = 0; j < 4; j++) acc[i][j] = 0ull;

    const size_t Pbase = (size_t)bh * L_ * L_;

    for (int sch = 0; sch < 1024 / SC3; sch++) {
        int sbase = zhalf * 1024 + sch * SC3;
        __syncthreads();
        for (int idx = tid; idx < SC3 * (TL3 / 4); idx += 256) {
            int sc = idx >> 5, c4 = idx & 31;
            float4 p = *(const float4*)&g_P[Pbase + (size_t)(sbase + sc) * L_ + lbase + 4 * c4];
            float iz = g_invZ[bh * L_ + sbase + sc];
            p.x *= iz; p.y *= iz; p.z *= iz; p.w *= iz;
            *(float4*)&Ws[sc][4 * c4] = p;
        }
        for (int idx = tid; idx < SC3 * (D_ / 4); idx += 256) {
            int sc = idx >> 4, d4 = idx & 15;
            *(float4*)&Vs[sc][4 * d4] =
                *(const float4*)&values[((size_t)(b * L_ + sbase + sc)) * E_ + h * D_ + 4 * d4];
        }
        __syncthreads();

#pragma unroll 4
        for (int sc = 0; sc < SC3; sc++) {
            ull2 w01 = *(const ull2*)&Ws[sc][8 * ty];       // broadcast
            ull2 w23 = *(const ull2*)&Ws[sc][8 * ty + 4];
            float4 bv = *(const float4*)&Vs[sc][4 * tx];    // conflict-free .128
            ull b0 = splat2(bv.x), b1 = splat2(bv.y), b2 = splat2(bv.z), b3 = splat2(bv.w);
            ffma2(acc[0][0], w01.x, b0); ffma2(acc[0][1], w01.x, b1);
            ffma2(acc[0][2], w01.x, b2); ffma2(acc[0][3], w01.x, b3);
            ffma2(acc[1][0], w01.y, b0); ffma2(acc[1][1], w01.y, b1);
            ffma2(acc[1][2], w01.y, b2); ffma2(acc[1][3], w01.y, b3);
            ffma2(acc[2][0], w23.x, b0); ffma2(acc[2][1], w23.x, b1);
            ffma2(acc[2][2], w23.x, b2); ffma2(acc[2][3], w23.x, b3);
            ffma2(acc[3][0], w23.y, b0); ffma2(acc[3][1], w23.y, b1);
            ffma2(acc[3][2], w23.y, b2); ffma2(acc[3][3], w23.y, b3);
        }
    }

    // store partial [z][bh][d][l]
#pragma unroll
    for (int jd = 0; jd < 4; jd++) {
        int dd = 4 * tx + jd;
        float* op = &g_Opart[(((size_t)zhalf * BH + bh) * D_ + dd) * L_ + lbase + 8 * ty];
        ull2 v0; v0.x = acc[0][jd]; v0.y = acc[1][jd];
        ull2 v1; v1.x = acc[2][jd]; v1.y = acc[3][jd];
        *(ull2*)&op[0] = v0;
        *(ull2*)&op[4] = v1;
    }
}

// ============ K3b: reduce partials + faithful scatter ============
__global__ void reduce_kernel(float* __restrict__ out) {
    int idx = blockIdx.x * blockDim.x + threadIdx.x;
    if (idx >= BH * D_ * L_) return;
    int l  = idx & (L_ - 1);
    int dd = (idx >> 11) & (D_ - 1);
    int bh = idx >> 17;
    int b  = bh >> 3, h = bh & 7;
    float v = g_Opart[idx] + g_Opart[BH * D_ * L_ + idx];
    int row = dd * 32 + h * 4 + (l >> 9);
    out[((size_t)b * 2048 + row) * 512 + (l & 511)] = v;
}

// ============ launch ============
extern "C" void kernel_launch(void* const* d_in, const int* in_sizes, int n_in,
                              void* d_out, int out_size) {
    (void)in_sizes; (void)n_in; (void)out_size;
    const float* q = (const float*)d_in[0];
    const float* k = (const float*)d_in[1];
    const float* v = (const float*)d_in[2];
    float* out = (float*)d_out;

    basis_kernel<<<(NC * L_ + 255) / 256, 256>>>();
    coeff_kernel<<<B_ * L_, 288>>>(q, k);
    z_kernel<<<dim3(L_ / TMZ, BH, 2), 256>>>();
    zcombine_kernel<<<(BH * L_ + 255) / 256, 256>>>();
    out_kernel<<<dim3(L_ / TL3, BH, 2), 256>>>(v);
    reduce_kernel<<<(BH * D_ * L_ + 255) / 256, 256>>>(out);
}